// round 1
// baseline (speedup 1.0000x reference)
#include <cuda_runtime.h>
#include <math.h>

#define NB 4
#define NN 256
#define OD 128

// ---------------- scratch (device globals; no allocation) ----------------
__device__ float g_f0a[NB * OD];
__device__ float g_f0b[NB * OD];
__device__ float g_f1a[NB * NN * OD];
__device__ float g_f1b[NB * NN * OD];
__device__ float g_f2a[(size_t)NB * NN * NN * OD];
__device__ float g_f2b[(size_t)NB * NN * NN * OD];
__device__ float g_r2[NB * NN * 2 * OD];
__device__ float g_Q[NB * NN * OD];
__device__ float g_P[NB * NN * OD];

__device__ __forceinline__ float sigmoidf_(float x) {
    return 1.0f / (1.0f + __expf(-x));
}

// ---------------- reduce2: [B,n,n,d2] -> [B,n,2*d2] (diag-masked max/min over j)
__global__ void k_reduce2(const float* __restrict__ f2, float* __restrict__ r2, int d2) {
    int i = blockIdx.x, b = blockIdx.y, d = threadIdx.x;
    if (d >= d2) return;
    const float* base = f2 + ((size_t)(b * NN + i)) * NN * d2 + d;
    float mx = -1e30f, mn = 1e30f;
    for (int j = 0; j < NN; j++) {
        float v = base[(size_t)j * d2];
        float vx = (j == i) ? 0.0f : v;
        float vn = (j == i) ? 1.0f : v;
        mx = fmaxf(mx, vx);
        mn = fminf(mn, vn);
    }
    r2[((size_t)(b * NN + i)) * 2 * d2 + d] = mx;
    r2[((size_t)(b * NN + i)) * 2 * d2 + d2 + d] = mn;
}

// ---------------- o0: g0 = [f0, max_n f1, min_n f1]; o0 = sigmoid(g0 @ W0 + b0)
__global__ void k_o0(const float* __restrict__ f0, const float* __restrict__ f1,
                     const float* __restrict__ W, const float* __restrict__ bias,
                     float* __restrict__ out, int d0, int d1) {
    __shared__ float sg[3 * OD];  // fan0 <= 384
    int b = blockIdx.x, t = threadIdx.x;
    if (t < d0) sg[t] = f0[b * d0 + t];
    if (t < d1) {
        float mx = -1e30f, mn = 1e30f;
        const float* base = f1 + (size_t)b * NN * d1 + t;
        for (int i = 0; i < NN; i++) {
            float v = base[(size_t)i * d1];
            mx = fmaxf(mx, v);
            mn = fminf(mn, v);
        }
        sg[d0 + t] = mx;
        sg[d0 + d1 + t] = mn;
    }
    __syncthreads();
    int fan = d0 + 2 * d1;
    float acc = bias[t];
    for (int k = 0; k < fan; k++) acc = fmaf(sg[k], W[(size_t)k * OD + t], acc);
    out[b * OD + t] = sigmoidf_(acc);
}

// ---------------- Q/P precompute: Q[row] = f1[row] @ Wa ; P[row] = f1[row] @ Wc
__global__ void k_qp(const float* __restrict__ f1, const float* __restrict__ Wa,
                     const float* __restrict__ Wc, float* __restrict__ Q,
                     float* __restrict__ P, int d1) {
    __shared__ float s[OD];
    int row = blockIdx.x;  // b*NN + i
    int t = threadIdx.x;
    if (t < d1) s[t] = f1[(size_t)row * d1 + t];
    __syncthreads();
    float aq = 0.0f, ap = 0.0f;
    for (int k = 0; k < d1; k++) {
        float v = s[k];
        aq = fmaf(v, Wa[(size_t)k * OD + t], aq);
        ap = fmaf(v, Wc[(size_t)k * OD + t], ap);
    }
    Q[(size_t)row * OD + t] = aq;
    P[(size_t)row * OD + t] = ap;
}

// ---------------- o1: g1 = [f0, f1[i], r2[i]] ; o1 = sigmoid(g1 @ W1 + b1)
#define O1R 8
__global__ void k_o1(const float* __restrict__ f0, const float* __restrict__ f1,
                     const float* __restrict__ r2, const float* __restrict__ W,
                     const float* __restrict__ bias, float* __restrict__ out,
                     int d0, int d1, int d2) {
    __shared__ float sg[O1R][512];
    int fan = d0 + d1 + 2 * d2;
    int row0 = blockIdx.x * O1R;
    int t = threadIdx.x;
    for (int idx = t; idx < O1R * fan; idx += OD) {
        int r = idx / fan, k = idx % fan;
        int row = row0 + r;
        int b = row / NN;
        float v;
        if (k < d0) v = f0[b * d0 + k];
        else if (k < d0 + d1) v = f1[(size_t)row * d1 + (k - d0)];
        else v = r2[(size_t)row * 2 * d2 + (k - d0 - d1)];
        sg[r][k] = v;
    }
    __syncthreads();
    float acc[O1R];
#pragma unroll
    for (int r = 0; r < O1R; r++) acc[r] = bias[t];
    for (int k = 0; k < fan; k++) {
        float w = W[(size_t)k * OD + t];
#pragma unroll
        for (int r = 0; r < O1R; r++) acc[r] = fmaf(sg[r][k], w, acc[r]);
    }
#pragma unroll
    for (int r = 0; r < O1R; r++)
        out[(size_t)(row0 + r) * OD + t] = sigmoidf_(acc[r]);
}

// ---------------- o2: fused tiled GEMM over K=2*d2 (f2[i,j] then f2[j,i])
// out[b,i,j,:] = sigmoid(f2[i,j]@Wb + f2[j,i]@Wd + Q[i] + P[j] + bias)
#define BM 64
#define BK 32
__global__ __launch_bounds__(256) void k_o2(
    const float* __restrict__ f2, const float* __restrict__ Q,
    const float* __restrict__ P, const float* __restrict__ Wb,
    const float* __restrict__ Wd, const float* __restrict__ bias,
    float* __restrict__ out, int d2) {
    __shared__ float sA[BM][BK];
    __shared__ float sB[BK][OD];
    int b = blockIdx.z, i = blockIdx.y, j0 = blockIdx.x * BM;
    int tx = threadIdx.x;
    int cg = tx & 31;   // col group: cols cg*4 .. cg*4+3
    int rg = tx >> 5;   // row group: rows rg*8 .. rg*8+7
    float acc[8][4];
#pragma unroll
    for (int r = 0; r < 8; r++)
#pragma unroll
        for (int c = 0; c < 4; c++) acc[r][c] = 0.0f;

    int K = 2 * d2;
    for (int c0 = 0; c0 < K; c0 += BK) {
        // stage A: 64 rows x 32 k (float4 per thread x2)
#pragma unroll
        for (int it = 0; it < 2; it++) {
            int t = tx + it * 256;
            int row = t >> 3;
            int kk4 = (t & 7) << 2;
            int k = c0 + kk4;
            int j = j0 + row;
            const float* src = (k < d2)
                ? f2 + (((size_t)(b * NN + i)) * NN + j) * d2 + k
                : f2 + (((size_t)(b * NN + j)) * NN + i) * d2 + (k - d2);
            *(float4*)&sA[row][kk4] = *(const float4*)src;
        }
        // stage B: 32 k x 128 cols (float4 per thread x4)
#pragma unroll
        for (int it = 0; it < 4; it++) {
            int t = tx + it * 256;
            int kk = t >> 5;
            int col = (t & 31) << 2;
            int k = c0 + kk;
            const float* src = (k < d2) ? Wb + (size_t)k * OD + col
                                        : Wd + (size_t)(k - d2) * OD + col;
            *(float4*)&sB[kk][col] = *(const float4*)src;
        }
        __syncthreads();
#pragma unroll
        for (int kk = 0; kk < BK; kk++) {
            float4 b4 = *(const float4*)&sB[kk][cg * 4];
#pragma unroll
            for (int r = 0; r < 8; r++) {
                float a = sA[rg * 8 + r][kk];
                acc[r][0] = fmaf(a, b4.x, acc[r][0]);
                acc[r][1] = fmaf(a, b4.y, acc[r][1]);
                acc[r][2] = fmaf(a, b4.z, acc[r][2]);
                acc[r][3] = fmaf(a, b4.w, acc[r][3]);
            }
        }
        __syncthreads();
    }

    float4 q4 = *(const float4*)(Q + ((size_t)(b * NN) + i) * OD + cg * 4);
    float4 bi4 = *(const float4*)(bias + cg * 4);
#pragma unroll
    for (int r = 0; r < 8; r++) {
        int j = j0 + rg * 8 + r;
        float4 p4 = *(const float4*)(P + ((size_t)(b * NN) + j) * OD + cg * 4);
        float4 o;
        o.x = sigmoidf_(acc[r][0] + q4.x + p4.x + bi4.x);
        o.y = sigmoidf_(acc[r][1] + q4.y + p4.y + bi4.y);
        o.z = sigmoidf_(acc[r][2] + q4.z + p4.z + bi4.z);
        o.w = sigmoidf_(acc[r][3] + q4.w + p4.w + bi4.w);
        *(float4*)(out + (((size_t)(b * NN) + i) * NN + j) * OD + cg * 4) = o;
    }
}

// ---------------- host side ----------------
static void run_layer(const float* f0, const float* f1, const float* f2,
                      int d0, int d1, int d2,
                      const float* W0, const float* b0,
                      const float* W1, const float* b1,
                      const float* W2, const float* b2,
                      float* o0, float* o1, float* o2,
                      float* r2, float* Q, float* P) {
    k_reduce2<<<dim3(NN, NB), d2>>>(f2, r2, d2);
    k_o0<<<NB, OD>>>(f0, f1, W0, b0, o0, d0, d1);
    const float* Wa = W2;
    const float* Wb = W2 + (size_t)d1 * OD;
    const float* Wc = W2 + (size_t)(d1 + d2) * OD;
    const float* Wd = W2 + (size_t)(2 * d1 + d2) * OD;
    k_qp<<<NB * NN, OD>>>(f1, Wa, Wc, Q, P, d1);
    k_o1<<<NB * NN / O1R, OD>>>(f0, f1, r2, W1, b1, o1, d0, d1, d2);
    k_o2<<<dim3(NN / BM, NN, NB), 256>>>(f2, Q, P, Wb, Wd, b2, o2, d2);
}

extern "C" void kernel_launch(void* const* d_in, const int* in_sizes, int n_in,
                              void* d_out, int out_size) {
    const float* x0 = (const float*)d_in[0];
    const float* x1 = (const float*)d_in[1];
    const float* x2 = (const float*)d_in[2];
    const float* W[3][3];
    const float* Bv[3][3];
    for (int l = 0; l < 3; l++)
        for (int o = 0; o < 3; o++) {
            W[l][o] = (const float*)d_in[3 + l * 6 + o * 2];
            Bv[l][o] = (const float*)d_in[3 + l * 6 + o * 2 + 1];
        }

    float *f0a, *f0b, *f1a, *f1b, *f2a, *f2b, *r2, *Q, *P;
    cudaGetSymbolAddress((void**)&f0a, g_f0a);
    cudaGetSymbolAddress((void**)&f0b, g_f0b);
    cudaGetSymbolAddress((void**)&f1a, g_f1a);
    cudaGetSymbolAddress((void**)&f1b, g_f1b);
    cudaGetSymbolAddress((void**)&f2a, g_f2a);
    cudaGetSymbolAddress((void**)&f2b, g_f2b);
    cudaGetSymbolAddress((void**)&r2, g_r2);
    cudaGetSymbolAddress((void**)&Q, g_Q);
    cudaGetSymbolAddress((void**)&P, g_P);

    float* out = (float*)d_out;
    float* out0 = out;
    float* out1 = out + NB * OD;
    float* out2 = out + NB * OD + (size_t)NB * NN * OD;

    // layer 0: dims (32, 64, 64) -> scratch A
    run_layer(x0, x1, x2, 32, 64, 64,
              W[0][0], Bv[0][0], W[0][1], Bv[0][1], W[0][2], Bv[0][2],
              f0a, f1a, f2a, r2, Q, P);
    // layer 1: dims (128,128,128) -> scratch B
    run_layer(f0a, f1a, f2a, 128, 128, 128,
              W[1][0], Bv[1][0], W[1][1], Bv[1][1], W[1][2], Bv[1][2],
              f0b, f1b, f2b, r2, Q, P);
    // layer 2: -> d_out (f0 | f1 | f2 flattened)
    run_layer(f0b, f1b, f2b, 128, 128, 128,
              W[2][0], Bv[2][0], W[2][1], Bv[2][1], W[2][2], Bv[2][2],
              out0, out1, out2, r2, Q, P);
}

// round 5
// speedup vs baseline: 1.9704x; 1.9704x over previous
#include <cuda_runtime.h>
#include <math.h>
#include <cstdint>

#define NB 4
#define NN 256
#define OD 128

// ---------------- scratch (device globals; no allocation) ----------------
__device__ float g_f0a[NB * OD];
__device__ float g_f0b[NB * OD];
__device__ float g_f1a[NB * NN * OD];
__device__ float g_f1b[NB * NN * OD];
__device__ float g_f2a[(size_t)NB * NN * NN * OD];
__device__ float g_f2b[(size_t)NB * NN * NN * OD];
__device__ float g_r2[NB * NN * 2 * OD];
__device__ float g_Q[NB * NN * OD];
__device__ float g_P[NB * NN * OD];
__device__ float g_Wt[2 * OD * OD];  // K-major, rna'd: Wt[k][n], k < 2*d2, n < 128

__device__ __forceinline__ float sigmoidf_(float x) {
    return 1.0f / (1.0f + __expf(-x));
}

__device__ __forceinline__ uint32_t smem_to_u32(const void* p) {
    uint32_t a;
    asm("{ .reg .u64 t; cvta.to.shared.u64 t, %1; cvt.u32.u64 %0, t; }" : "=r"(a) : "l"(p));
    return a;
}
__device__ __forceinline__ uint32_t cvt_rna_tf32(float f) {
    uint32_t r;
    asm("cvt.rna.tf32.f32 %0, %1;" : "=r"(r) : "f"(f));
    return r;
}
#define CP_ASYNC16(dst, src) \
    asm volatile("cp.async.cg.shared.global [%0], [%1], 16;" :: "r"(dst), "l"(src) : "memory")
#define CP_COMMIT() asm volatile("cp.async.commit_group;" ::: "memory")
#define CP_WAIT(n) asm volatile("cp.async.wait_group %0;" :: "n"(n) : "memory")

// mma.sync m16n8k8 tf32 (sm_80+, works on plain sm_103 target)
__device__ __forceinline__ void mma_tf32(float* d, const uint32_t* a, const uint32_t* b) {
    asm volatile(
        "mma.sync.aligned.m16n8k8.row.col.f32.tf32.tf32.f32 "
        "{%0,%1,%2,%3}, {%4,%5,%6,%7}, {%8,%9}, {%0,%1,%2,%3};"
        : "+f"(d[0]), "+f"(d[1]), "+f"(d[2]), "+f"(d[3])
        : "r"(a[0]), "r"(a[1]), "r"(a[2]), "r"(a[3]), "r"(b[0]), "r"(b[1]));
}

// ---------------- reduce2: [B,n,n,d2] -> [B,n,2*d2] (diag-masked max/min over j)
__global__ void k_reduce2(const float* __restrict__ f2, float* __restrict__ r2, int d2) {
    int i = blockIdx.x, b = blockIdx.y, d = threadIdx.x;
    if (d >= d2) return;
    const float* base = f2 + ((size_t)(b * NN + i)) * NN * d2 + d;
    float mx = -1e30f, mn = 1e30f;
    for (int j = 0; j < NN; j++) {
        float v = base[(size_t)j * d2];
        float vx = (j == i) ? 0.0f : v;
        float vn = (j == i) ? 1.0f : v;
        mx = fmaxf(mx, vx);
        mn = fminf(mn, vn);
    }
    r2[((size_t)(b * NN + i)) * 2 * d2 + d] = mx;
    r2[((size_t)(b * NN + i)) * 2 * d2 + d2 + d] = mn;
}

// ---------------- o0 ----------------
__global__ void k_o0(const float* __restrict__ f0, const float* __restrict__ f1,
                     const float* __restrict__ W, const float* __restrict__ bias,
                     float* __restrict__ out, int d0, int d1) {
    __shared__ float sg[3 * OD];
    int b = blockIdx.x, t = threadIdx.x;
    if (t < d0) sg[t] = f0[b * d0 + t];
    if (t < d1) {
        float mx = -1e30f, mn = 1e30f;
        const float* base = f1 + (size_t)b * NN * d1 + t;
        for (int i = 0; i < NN; i++) {
            float v = base[(size_t)i * d1];
            mx = fmaxf(mx, v);
            mn = fminf(mn, v);
        }
        sg[d0 + t] = mx;
        sg[d0 + d1 + t] = mn;
    }
    __syncthreads();
    int fan = d0 + 2 * d1;
    float acc = bias[t];
    for (int k = 0; k < fan; k++) acc = fmaf(sg[k], W[(size_t)k * OD + t], acc);
    out[b * OD + t] = sigmoidf_(acc);
}

// ---------------- Q/P: Q[row] = f1[row] @ Wa ; P[row] = f1[row] @ Wc ----------
__global__ void k_qp(const float* __restrict__ f1, const float* __restrict__ Wa,
                     const float* __restrict__ Wc, float* __restrict__ Q,
                     float* __restrict__ P, int d1) {
    __shared__ float s[OD];
    int row = blockIdx.x;
    int t = threadIdx.x;
    if (t < d1) s[t] = f1[(size_t)row * d1 + t];
    __syncthreads();
    float aq = 0.0f, ap = 0.0f;
    for (int k = 0; k < d1; k++) {
        float v = s[k];
        aq = fmaf(v, Wa[(size_t)k * OD + t], aq);
        ap = fmaf(v, Wc[(size_t)k * OD + t], ap);
    }
    Q[(size_t)row * OD + t] = aq;
    P[(size_t)row * OD + t] = ap;
}

// ---------------- o1 ----------------
#define O1R 2
__global__ void k_o1(const float* __restrict__ f0, const float* __restrict__ f1,
                     const float* __restrict__ r2, const float* __restrict__ W,
                     const float* __restrict__ bias, float* __restrict__ out,
                     int d0, int d1, int d2) {
    __shared__ float sg[O1R][512];
    int fan = d0 + d1 + 2 * d2;
    int row0 = blockIdx.x * O1R;
    int t = threadIdx.x;
    for (int idx = t; idx < O1R * fan; idx += OD) {
        int r = idx / fan, k = idx % fan;
        int row = row0 + r;
        int b = row / NN;
        float v;
        if (k < d0) v = f0[b * d0 + k];
        else if (k < d0 + d1) v = f1[(size_t)row * d1 + (k - d0)];
        else v = r2[(size_t)row * 2 * d2 + (k - d0 - d1)];
        sg[r][k] = v;
    }
    __syncthreads();
    float acc[O1R];
#pragma unroll
    for (int r = 0; r < O1R; r++) acc[r] = bias[t];
    for (int k = 0; k < fan; k++) {
        float w = W[(size_t)k * OD + t];
#pragma unroll
        for (int r = 0; r < O1R; r++) acc[r] = fmaf(sg[r][k], w, acc[r]);
    }
#pragma unroll
    for (int r = 0; r < O1R; r++)
        out[(size_t)(row0 + r) * OD + t] = sigmoidf_(acc[r]);
}

// ---------------- weight transpose + rna: Wt[k][n] (K-major) ----------------
__global__ void k_wt(const float* __restrict__ W2, float* __restrict__ Wt,
                     int d1, int d2) {
    int k = blockIdx.x, n = threadIdx.x;
    const float* src = (k < d2) ? W2 + (size_t)(d1 + k) * OD + n
                                : W2 + (size_t)(2 * d1 + d2 + (k - d2)) * OD + n;
    Wt[(size_t)k * OD + n] = __uint_as_float(cvt_rna_tf32(*src));
}

// ---------------- o2: mma.sync tf32, M=128 (j-tile) x N=128, K=2*D2 ----------
// out[b,i,j,:] = sigmoid(f2[i,j]@Wb + f2[j,i]@Wd + Q[i] + P[j] + bias)
#define AST 36    // A smem row stride (words)
#define BST 132   // B smem row stride (words)
#define ABUF (128 * AST)
#define BBUF (32 * BST)
#define O2_SMEM ((2 * ABUF + 2 * BBUF) * 4)

template <int D2>
__global__ void __launch_bounds__(256, 2) k_o2m(
    const float* __restrict__ f2, const float* __restrict__ Q,
    const float* __restrict__ P, const float* __restrict__ Wt,
    const float* __restrict__ bias, float* __restrict__ out) {
    constexpr int K = 2 * D2;
    constexpr int NS = K / 32;

    extern __shared__ uint32_t smw[];
    uint32_t* Ab = smw;                 // 2 * ABUF words
    uint32_t* Bb = smw + 2 * ABUF;      // 2 * BBUF words
    uint32_t sb_addr = smem_to_u32(Bb);

    int tx = threadIdx.x;
    int lane = tx & 31, warp = tx >> 5;
    int warpM = warp & 1, warpN = warp >> 1;
    int gi = lane >> 2, ci = lane & 3;
    int b = blockIdx.z, i = blockIdx.y, j0 = blockIdx.x * 128;
    size_t bi = ((size_t)(b * NN + i)) * NN;

    // per-iteration A gmem bases (row j fixed per it, k varies per stage)
    const float* aH1[4];  // k < D2 half:  f2[b,i,j] rows
    const float* aH2[4];  // k >= D2 half: f2[b,j,i] rows (pre-shifted by -D2)
#pragma unroll
    for (int it = 0; it < 4; it++) {
        int rowj = j0 + ((tx + it * 256) >> 3);
        aH1[it] = f2 + (bi + rowj) * D2;
        aH2[it] = f2 + (((size_t)(b * NN + rowj)) * NN + i) * D2 - D2;
    }

    float acc[4][4][4];
#pragma unroll
    for (int mt = 0; mt < 4; mt++)
#pragma unroll
        for (int nt = 0; nt < 4; nt++)
#pragma unroll
            for (int v = 0; v < 4; v++) acc[mt][nt][v] = 0.0f;

    // --- prologue: issue B(0) cp.async, load A(0) into regs
    {
#pragma unroll
        for (int it = 0; it < 4; it++) {
            int t = tx + it * 256;
            int row = t >> 5, col4 = t & 31;
            uint32_t dst = sb_addr + (uint32_t)(row * BST + col4 * 4) * 4u;
            CP_ASYNC16(dst, Wt + (size_t)row * OD + col4 * 4);
        }
        CP_COMMIT();
    }
    float4 ra[4];
#pragma unroll
    for (int it = 0; it < 4; it++) {
        int q = (tx + it * 256) & 7;
        ra[it] = *(const float4*)(aH1[it] + q * 4);  // stage 0: c0=0 < D2
    }

    for (int s = 0; s < NS; s++) {
        int p = s & 1;
        // store A regs (stage s) with rna conversion
#pragma unroll
        for (int it = 0; it < 4; it++) {
            int t = tx + it * 256;
            int row = t >> 3, q = t & 7;
            uint32_t* d = Ab + p * ABUF + row * AST + q * 4;
            uint4 c;
            c.x = cvt_rna_tf32(ra[it].x);
            c.y = cvt_rna_tf32(ra[it].y);
            c.z = cvt_rna_tf32(ra[it].z);
            c.w = cvt_rna_tf32(ra[it].w);
            *(uint4*)d = c;
        }
        __syncthreads();  // A(s) visible; all warps past mma(s-1) -> safe to overwrite Bb[p^1]
        if (s + 1 < NS) {
            int c0n = (s + 1) * 32;
#pragma unroll
            for (int it = 0; it < 4; it++) {
                int t = tx + it * 256;
                int row = t >> 5, col4 = t & 31;
                uint32_t dst = sb_addr + (uint32_t)((p ^ 1) * BBUF + row * BST + col4 * 4) * 4u;
                CP_ASYNC16(dst, Wt + (size_t)(c0n + row) * OD + col4 * 4);
            }
            CP_COMMIT();
            CP_WAIT(1);  // B(s) complete (this thread)
        } else {
            CP_WAIT(0);
        }
        __syncthreads();  // B(s) visible to all
        if (s + 1 < NS) {
            int c0n = (s + 1) * 32;
#pragma unroll
            for (int it = 0; it < 4; it++) {
                int q = (tx + it * 256) & 7;
                const float* base = (c0n < D2) ? aH1[it] : aH2[it];
                ra[it] = *(const float4*)(base + c0n + q * 4);
            }
        }
        // --- mma on stage s
        const uint32_t* As = Ab + p * ABUF;
        const uint32_t* Bs = Bb + p * BBUF;
#pragma unroll
        for (int ks = 0; ks < 4; ks++) {
            uint32_t af[4][4];
#pragma unroll
            for (int mt = 0; mt < 4; mt++) {
                const uint32_t* ab = As + (warpM * 64 + mt * 16 + gi) * AST + ks * 8 + ci;
                af[mt][0] = ab[0];
                af[mt][1] = ab[8 * AST];
                af[mt][2] = ab[4];
                af[mt][3] = ab[8 * AST + 4];
            }
            uint32_t bf[4][2];
#pragma unroll
            for (int nt = 0; nt < 4; nt++) {
                const uint32_t* bb = Bs + (ks * 8 + ci) * BST + warpN * 32 + nt * 8 + gi;
                bf[nt][0] = bb[0];
                bf[nt][1] = bb[4 * BST];
            }
#pragma unroll
            for (int mt = 0; mt < 4; mt++)
#pragma unroll
                for (int nt = 0; nt < 4; nt++)
                    mma_tf32(acc[mt][nt], af[mt], bf[nt]);
        }
    }

    // --- epilogue
    __syncthreads();
    float* sQB = (float*)smw;  // reuse A buffer region
    if (tx < 128) sQB[tx] = Q[((size_t)(b * NN + i)) * OD + tx] + bias[tx];
    __syncthreads();
#pragma unroll
    for (int mt = 0; mt < 4; mt++) {
#pragma unroll
        for (int rr = 0; rr < 2; rr++) {
            int j = j0 + warpM * 64 + mt * 16 + gi + rr * 8;
            const float* pRow = P + ((size_t)(b * NN + j)) * OD;
            float* oRow = out + (bi + j) * OD;
#pragma unroll
            for (int nt = 0; nt < 4; nt++) {
                int col = warpN * 32 + nt * 8 + ci * 2;
                float2 p2 = *(const float2*)(pRow + col);
                float2 o;
                o.x = sigmoidf_(acc[mt][nt][rr * 2 + 0] + sQB[col + 0] + p2.x);
                o.y = sigmoidf_(acc[mt][nt][rr * 2 + 1] + sQB[col + 1] + p2.y);
                *(float2*)(oRow + col) = o;
            }
        }
    }
}

// ---------------- host side ----------------
template <int D2>
static void run_layer(const float* f0, const float* f1, const float* f2,
                      int d0, int d1,
                      const float* W0, const float* b0,
                      const float* W1, const float* b1,
                      const float* W2, const float* b2,
                      float* o0, float* o1, float* o2,
                      float* r2, float* Q, float* P, float* Wt) {
    cudaFuncSetAttribute(k_o2m<D2>, cudaFuncAttributeMaxDynamicSharedMemorySize, O2_SMEM);
    k_reduce2<<<dim3(NN, NB), D2>>>(f2, r2, D2);
    k_o0<<<NB, OD>>>(f0, f1, W0, b0, o0, d0, d1);
    const float* Wa = W2;
    const float* Wc = W2 + (size_t)(d1 + D2) * OD;
    k_wt<<<2 * D2, OD>>>(W2, Wt, d1, D2);
    k_qp<<<NB * NN, OD>>>(f1, Wa, Wc, Q, P, d1);
    k_o1<<<NB * NN / O1R, OD>>>(f0, f1, r2, W1, b1, o1, d0, d1, D2);
    k_o2m<D2><<<dim3(NN / 128, NN, NB), 256, O2_SMEM>>>(f2, Q, P, Wt, b2, o2);
}

extern "C" void kernel_launch(void* const* d_in, const int* in_sizes, int n_in,
                              void* d_out, int out_size) {
    const float* x0 = (const float*)d_in[0];
    const float* x1 = (const float*)d_in[1];
    const float* x2 = (const float*)d_in[2];
    const float* W[3][3];
    const float* Bv[3][3];
    for (int l = 0; l < 3; l++)
        for (int o = 0; o < 3; o++) {
            W[l][o] = (const float*)d_in[3 + l * 6 + o * 2];
            Bv[l][o] = (const float*)d_in[3 + l * 6 + o * 2 + 1];
        }

    float *f0a, *f0b, *f1a, *f1b, *f2a, *f2b, *r2, *Q, *P, *Wt;
    cudaGetSymbolAddress((void**)&f0a, g_f0a);
    cudaGetSymbolAddress((void**)&f0b, g_f0b);
    cudaGetSymbolAddress((void**)&f1a, g_f1a);
    cudaGetSymbolAddress((void**)&f1b, g_f1b);
    cudaGetSymbolAddress((void**)&f2a, g_f2a);
    cudaGetSymbolAddress((void**)&f2b, g_f2b);
    cudaGetSymbolAddress((void**)&r2, g_r2);
    cudaGetSymbolAddress((void**)&Q, g_Q);
    cudaGetSymbolAddress((void**)&P, g_P);
    cudaGetSymbolAddress((void**)&Wt, g_Wt);

    float* out = (float*)d_out;
    float* out0 = out;
    float* out1 = out + NB * OD;
    float* out2 = out + NB * OD + (size_t)NB * NN * OD;

    run_layer<64>(x0, x1, x2, 32, 64,
                  W[0][0], Bv[0][0], W[0][1], Bv[0][1], W[0][2], Bv[0][2],
                  f0a, f1a, f2a, r2, Q, P, Wt);
    run_layer<128>(f0a, f1a, f2a, 128, 128,
                   W[1][0], Bv[1][0], W[1][1], Bv[1][1], W[1][2], Bv[1][2],
                   f0b, f1b, f2b, r2, Q, P, Wt);
    run_layer<128>(f0b, f1b, f2b, 128, 128,
                   W[2][0], Bv[2][0], W[2][1], Bv[2][1], W[2][2], Bv[2][2],
                   out0, out1, out2, r2, Q, P, Wt);
}

// round 7
// speedup vs baseline: 2.2458x; 1.1398x over previous
#include <cuda_runtime.h>
#include <cuda_fp16.h>
#include <math.h>
#include <cstdint>

#define NB 4
#define NN 256
#define OD 128

// ---------------- scratch (device globals; no allocation) ----------------
__device__ float g_f0a[NB * OD];
__device__ float g_f0b[NB * OD];
__device__ float g_f1a[NB * NN * OD];
__device__ float g_f1b[NB * NN * OD];
__device__ float g_f2a[(size_t)NB * NN * NN * OD];
__device__ float g_f2b[(size_t)NB * NN * NN * OD];
__device__ float g_r2[NB * NN * 2 * OD];
__device__ float g_Q[NB * NN * OD];
__device__ float g_P[NB * NN * OD];
__device__ __half g_Wt[OD * 2 * OD];  // n-major fp16: Wt[n][k], n<128, k<2*d2

__device__ __forceinline__ float sigmoidf_(float x) {
    return 1.0f / (1.0f + __expf(-x));
}

__device__ __forceinline__ uint32_t smem_to_u32(const void* p) {
    uint32_t a;
    asm("{ .reg .u64 t; cvta.to.shared.u64 t, %1; cvt.u32.u64 %0, t; }" : "=r"(a) : "l"(p));
    return a;
}
// pack two fp32 -> one f16x2 register (lo = x, hi = y)
__device__ __forceinline__ uint32_t pack_f16x2(float x, float y) {
    uint32_t r;
    asm("cvt.rn.f16x2.f32 %0, %2, %1;" : "=r"(r) : "f"(x), "f"(y));
    return r;
}
#define CP_ASYNC16(dst, src) \
    asm volatile("cp.async.cg.shared.global [%0], [%1], 16;" :: "r"(dst), "l"(src) : "memory")
#define CP_COMMIT() asm volatile("cp.async.commit_group;" ::: "memory")
#define CP_WAIT(n) asm volatile("cp.async.wait_group %0;" :: "n"(n) : "memory")

// mma.sync m16n8k16 f16 -> f32 acc (sm_80+, legal on plain sm_103 target)
__device__ __forceinline__ void mma_f16(float* d, const uint32_t* a, const uint32_t* b) {
    asm volatile(
        "mma.sync.aligned.m16n8k16.row.col.f32.f16.f16.f32 "
        "{%0,%1,%2,%3}, {%4,%5,%6,%7}, {%8,%9}, {%0,%1,%2,%3};"
        : "+f"(d[0]), "+f"(d[1]), "+f"(d[2]), "+f"(d[3])
        : "r"(a[0]), "r"(a[1]), "r"(a[2]), "r"(a[3]), "r"(b[0]), "r"(b[1]));
}

// ---------------- reduce2: [B,n,n,d2] -> [B,n,2*d2] (diag-masked max/min over j)
__global__ void k_reduce2(const float* __restrict__ f2, float* __restrict__ r2, int d2) {
    int i = blockIdx.x, b = blockIdx.y, d = threadIdx.x;
    if (d >= d2) return;
    const float* base = f2 + ((size_t)(b * NN + i)) * NN * d2 + d;
    float mx = -1e30f, mn = 1e30f;
    for (int j = 0; j < NN; j++) {
        float v = base[(size_t)j * d2];
        float vx = (j == i) ? 0.0f : v;
        float vn = (j == i) ? 1.0f : v;
        mx = fmaxf(mx, vx);
        mn = fminf(mn, vn);
    }
    r2[((size_t)(b * NN + i)) * 2 * d2 + d] = mx;
    r2[((size_t)(b * NN + i)) * 2 * d2 + d2 + d] = mn;
}

// ---------------- o0 ----------------
__global__ void k_o0(const float* __restrict__ f0, const float* __restrict__ f1,
                     const float* __restrict__ W, const float* __restrict__ bias,
                     float* __restrict__ out, int d0, int d1) {
    __shared__ float sg[3 * OD];
    int b = blockIdx.x, t = threadIdx.x;
    if (t < d0) sg[t] = f0[b * d0 + t];
    if (t < d1) {
        float mx = -1e30f, mn = 1e30f;
        const float* base = f1 + (size_t)b * NN * d1 + t;
        for (int i = 0; i < NN; i++) {
            float v = base[(size_t)i * d1];
            mx = fmaxf(mx, v);
            mn = fminf(mn, v);
        }
        sg[d0 + t] = mx;
        sg[d0 + d1 + t] = mn;
    }
    __syncthreads();
    int fan = d0 + 2 * d1;
    float acc = bias[t];
    for (int k = 0; k < fan; k++) acc = fmaf(sg[k], W[(size_t)k * OD + t], acc);
    out[b * OD + t] = sigmoidf_(acc);
}

// ---------------- Q/P ----------------
__global__ void k_qp(const float* __restrict__ f1, const float* __restrict__ Wa,
                     const float* __restrict__ Wc, float* __restrict__ Q,
                     float* __restrict__ P, int d1) {
    __shared__ float s[OD];
    int row = blockIdx.x;
    int t = threadIdx.x;
    if (t < d1) s[t] = f1[(size_t)row * d1 + t];
    __syncthreads();
    float aq = 0.0f, ap = 0.0f;
    for (int k = 0; k < d1; k++) {
        float v = s[k];
        aq = fmaf(v, Wa[(size_t)k * OD + t], aq);
        ap = fmaf(v, Wc[(size_t)k * OD + t], ap);
    }
    Q[(size_t)row * OD + t] = aq;
    P[(size_t)row * OD + t] = ap;
}

// ---------------- o1 ----------------
#define O1R 2
__global__ void k_o1(const float* __restrict__ f0, const float* __restrict__ f1,
                     const float* __restrict__ r2, const float* __restrict__ W,
                     const float* __restrict__ bias, float* __restrict__ out,
                     int d0, int d1, int d2) {
    __shared__ float sg[O1R][512];
    int fan = d0 + d1 + 2 * d2;
    int row0 = blockIdx.x * O1R;
    int t = threadIdx.x;
    for (int idx = t; idx < O1R * fan; idx += OD) {
        int r = idx / fan, k = idx % fan;
        int row = row0 + r;
        int b = row / NN;
        float v;
        if (k < d0) v = f0[b * d0 + k];
        else if (k < d0 + d1) v = f1[(size_t)row * d1 + (k - d0)];
        else v = r2[(size_t)row * 2 * d2 + (k - d0 - d1)];
        sg[r][k] = v;
    }
    __syncthreads();
    float acc[O1R];
#pragma unroll
    for (int r = 0; r < O1R; r++) acc[r] = bias[t];
    for (int k = 0; k < fan; k++) {
        float w = W[(size_t)k * OD + t];
#pragma unroll
        for (int r = 0; r < O1R; r++) acc[r] = fmaf(sg[r][k], w, acc[r]);
    }
#pragma unroll
    for (int r = 0; r < O1R; r++)
        out[(size_t)(row0 + r) * OD + t] = sigmoidf_(acc[r]);
}

// ---------------- weight transpose + fp16: Wt[n][k] (n-major, k contiguous) --
__global__ void k_wt(const float* __restrict__ W2, __half* __restrict__ Wt,
                     int d1, int d2) {
    int n = blockIdx.x;  // 0..127
    int K = 2 * d2;
    for (int k = threadIdx.x; k < K; k += blockDim.x) {
        const float* src = (k < d2) ? W2 + (size_t)(d1 + k) * OD + n
                                    : W2 + (size_t)(2 * d1 + d2 + (k - d2)) * OD + n;
        Wt[(size_t)n * K + k] = __float2half_rn(*src);
    }
}

// ---------------- o2: mma.sync fp16, M=128 (j-tile) x N=128, K=2*D2 ----------
// out[b,i,j,:] = sigmoid(f2[i,j]@Wb + f2[j,i]@Wd + Q[i] + P[j] + bias)
#define AST 20    // A smem row stride in 32-bit words (32 halves = 16 words + pad 4)
#define BST 20    // B smem row stride in words
#define ABUF (128 * AST)
#define BBUF (128 * BST)
#define O2_SMEM ((2 * ABUF + 2 * BBUF) * 4)

template <int D2>
__global__ void __launch_bounds__(256, 2) k_o2m(
    const float* __restrict__ f2, const float* __restrict__ Q,
    const float* __restrict__ P, const __half* __restrict__ Wt,
    const float* __restrict__ bias, float* __restrict__ out) {
    constexpr int K = 2 * D2;
    constexpr int NS = K / 32;

    extern __shared__ uint32_t smw[];
    uint32_t* Ab = smw;                 // 2 * ABUF words
    uint32_t* Bb = smw + 2 * ABUF;      // 2 * BBUF words
    uint32_t sb_addr = smem_to_u32(Bb);

    int tx = threadIdx.x;
    int lane = tx & 31, warp = tx >> 5;
    int warpM = warp & 1, warpN = warp >> 1;
    int gi = lane >> 2, ci = lane & 3;
    int b = blockIdx.z, i = blockIdx.y, j0 = blockIdx.x * 128;
    size_t bi = ((size_t)(b * NN + i)) * NN;

    // per-iteration A gmem bases
    const float* aH1[4];  // k < D2 half:  f2[b,i,j] rows
    const float* aH2[4];  // k >= D2 half: f2[b,j,i] rows (pre-shifted by -D2)
#pragma unroll
    for (int it = 0; it < 4; it++) {
        int rowj = j0 + ((tx + it * 256) >> 3);
        aH1[it] = f2 + (bi + rowj) * D2;
        aH2[it] = f2 + (((size_t)(b * NN + rowj)) * NN + i) * D2 - D2;
    }

    float acc[4][4][4];
#pragma unroll
    for (int mt = 0; mt < 4; mt++)
#pragma unroll
        for (int nt = 0; nt < 4; nt++)
#pragma unroll
            for (int v = 0; v < 4; v++) acc[mt][nt][v] = 0.0f;

    // --- prologue: issue B(0) cp.async (8KB: 128 n-rows x 32 halves)
    {
#pragma unroll
        for (int it = 0; it < 2; it++) {
            int t = tx + it * 256;
            int row = t >> 2, chunk = t & 3;  // chunk = 16B = 8 halves
            uint32_t dst = sb_addr + (uint32_t)(row * BST + chunk * 4) * 4u;
            CP_ASYNC16(dst, Wt + (size_t)row * K + chunk * 8);
        }
        CP_COMMIT();
    }
    float4 ra[4];
#pragma unroll
    for (int it = 0; it < 4; it++) {
        int q = (tx + it * 256) & 7;
        ra[it] = *(const float4*)(aH1[it] + q * 4);  // stage 0: c0=0 < D2
    }

    for (int s = 0; s < NS; s++) {
        int p = s & 1;
        // store A regs (stage s) converted to fp16
#pragma unroll
        for (int it = 0; it < 4; it++) {
            int t = tx + it * 256;
            int row = t >> 3, q = t & 7;  // halves q*4..q*4+3 -> words q*2, q*2+1
            uint2 v;
            v.x = pack_f16x2(ra[it].x, ra[it].y);
            v.y = pack_f16x2(ra[it].z, ra[it].w);
            *(uint2*)(Ab + p * ABUF + row * AST + q * 2) = v;
        }
        __syncthreads();  // A(s) visible; all warps past mma(s-1)
        if (s + 1 < NS) {
            int c0n = (s + 1) * 32;
#pragma unroll
            for (int it = 0; it < 2; it++) {
                int t = tx + it * 256;
                int row = t >> 2, chunk = t & 3;
                uint32_t dst = sb_addr + (uint32_t)((p ^ 1) * BBUF + row * BST + chunk * 4) * 4u;
                CP_ASYNC16(dst, Wt + (size_t)row * K + c0n + chunk * 8);
            }
            CP_COMMIT();
            CP_WAIT(1);  // B(s) complete (this thread)
        } else {
            CP_WAIT(0);
        }
        __syncthreads();  // B(s) visible to all
        if (s + 1 < NS) {
            int c0n = (s + 1) * 32;
#pragma unroll
            for (int it = 0; it < 4; it++) {
                int q = (tx + it * 256) & 7;
                const float* base = (c0n < D2) ? aH1[it] : aH2[it];
                ra[it] = *(const float4*)(base + c0n + q * 4);
            }
        }
        // --- mma on stage s: 2 k16 chunks
        const uint32_t* As = Ab + p * ABUF;
        const uint32_t* Bs = Bb + p * BBUF;
#pragma unroll
        for (int ks = 0; ks < 2; ks++) {
            uint32_t af[4][4];
#pragma unroll
            for (int mt = 0; mt < 4; mt++) {
                const uint32_t* ab = As + (warpM * 64 + mt * 16 + gi) * AST + ks * 8 + ci;
                af[mt][0] = ab[0];
                af[mt][1] = ab[8 * AST];
                af[mt][2] = ab[4];
                af[mt][3] = ab[8 * AST + 4];
            }
            uint32_t bf[4][2];
#pragma unroll
            for (int nt = 0; nt < 4; nt++) {
                const uint32_t* bb = Bs + (warpN * 32 + nt * 8 + gi) * BST + ks * 8 + ci;
                bf[nt][0] = bb[0];
                bf[nt][1] = bb[4];
            }
#pragma unroll
            for (int mt = 0; mt < 4; mt++)
#pragma unroll
                for (int nt = 0; nt < 4; nt++)
                    mma_f16(acc[mt][nt], af[mt], bf[nt]);
        }
    }

    // --- epilogue
    __syncthreads();
    float* sQB = (float*)smw;  // reuse A buffer region
    if (tx < 128) sQB[tx] = Q[((size_t)(b * NN + i)) * OD + tx] + bias[tx];
    __syncthreads();
#pragma unroll
    for (int mt = 0; mt < 4; mt++) {
#pragma unroll
        for (int rr = 0; rr < 2; rr++) {
            int j = j0 + warpM * 64 + mt * 16 + gi + rr * 8;
            const float* pRow = P + ((size_t)(b * NN + j)) * OD;
            float* oRow = out + (bi + j) * OD;
#pragma unroll
            for (int nt = 0; nt < 4; nt++) {
                int col = warpN * 32 + nt * 8 + ci * 2;
                float2 p2 = *(const float2*)(pRow + col);
                float2 o;
                o.x = sigmoidf_(acc[mt][nt][rr * 2 + 0] + sQB[col + 0] + p2.x);
                o.y = sigmoidf_(acc[mt][nt][rr * 2 + 1] + sQB[col + 1] + p2.y);
                *(float2*)(oRow + col) = o;
            }
        }
    }
}

// ---------------- host side ----------------
template <int D2>
static void run_layer(const float* f0, const float* f1, const float* f2,
                      int d0, int d1,
                      const float* W0, const float* b0,
                      const float* W1, const float* b1,
                      const float* W2, const float* b2,
                      float* o0, float* o1, float* o2,
                      float* r2, float* Q, float* P, __half* Wt) {
    cudaFuncSetAttribute(k_o2m<D2>, cudaFuncAttributeMaxDynamicSharedMemorySize, O2_SMEM);
    k_reduce2<<<dim3(NN, NB), D2>>>(f2, r2, D2);
    k_o0<<<NB, OD>>>(f0, f1, W0, b0, o0, d0, d1);
    const float* Wa = W2;
    const float* Wc = W2 + (size_t)(d1 + D2) * OD;
    k_wt<<<OD, 256>>>(W2, Wt, d1, D2);
    k_qp<<<NB * NN, OD>>>(f1, Wa, Wc, Q, P, d1);
    k_o1<<<NB * NN / O1R, OD>>>(f0, f1, r2, W1, b1, o1, d0, d1, D2);
    k_o2m<D2><<<dim3(NN / 128, NN, NB), 256, O2_SMEM>>>(f2, Q, P, Wt, b2, o2);
}

extern "C" void kernel_launch(void* const* d_in, const int* in_sizes, int n_in,
                              void* d_out, int out_size) {
    const float* x0 = (const float*)d_in[0];
    const float* x1 = (const float*)d_in[1];
    const float* x2 = (const float*)d_in[2];
    const float* W[3][3];
    const float* Bv[3][3];
    for (int l = 0; l < 3; l++)
        for (int o = 0; o < 3; o++) {
            W[l][o] = (const float*)d_in[3 + l * 6 + o * 2];
            Bv[l][o] = (const float*)d_in[3 + l * 6 + o * 2 + 1];
        }

    float *f0a, *f0b, *f1a, *f1b, *f2a, *f2b, *r2, *Q, *P;
    __half* Wt;
    cudaGetSymbolAddress((void**)&f0a, g_f0a);
    cudaGetSymbolAddress((void**)&f0b, g_f0b);
    cudaGetSymbolAddress((void**)&f1a, g_f1a);
    cudaGetSymbolAddress((void**)&f1b, g_f1b);
    cudaGetSymbolAddress((void**)&f2a, g_f2a);
    cudaGetSymbolAddress((void**)&f2b, g_f2b);
    cudaGetSymbolAddress((void**)&r2, g_r2);
    cudaGetSymbolAddress((void**)&Q, g_Q);
    cudaGetSymbolAddress((void**)&P, g_P);
    cudaGetSymbolAddress((void**)&Wt, g_Wt);

    float* out = (float*)d_out;
    float* out0 = out;
    float* out1 = out + NB * OD;
    float* out2 = out + NB * OD + (size_t)NB * NN * OD;

    run_layer<64>(x0, x1, x2, 32, 64,
                  W[0][0], Bv[0][0], W[0][1], Bv[0][1], W[0][2], Bv[0][2],
                  f0a, f1a, f2a, r2, Q, P, Wt);
    run_layer<128>(f0a, f1a, f2a, 128, 128,
                   W[1][0], Bv[1][0], W[1][1], Bv[1][1], W[1][2], Bv[1][2],
                   f0b, f1b, f2b, r2, Q, P, Wt);
    run_layer<128>(f0b, f1b, f2b, 128, 128,
                   W[2][0], Bv[2][0], W[2][1], Bv[2][1], W[2][2], Bv[2][2],
                   out0, out1, out2, r2, Q, P, Wt);
}

// round 8
// speedup vs baseline: 2.4851x; 1.1066x over previous
#include <cuda_runtime.h>
#include <cuda_fp16.h>
#include <math.h>
#include <cstdint>

#define NB 4
#define NN 256
#define OD 128

// ---------------- scratch (device globals; no allocation) ----------------
__device__ float g_f0a[NB * OD];
__device__ float g_f0b[NB * OD];
__device__ float g_f1a[NB * NN * OD];
__device__ float g_f1b[NB * NN * OD];
__device__ float g_f2a[(size_t)NB * NN * NN * OD];
__device__ float g_f2b[(size_t)NB * NN * NN * OD];
__device__ float g_r2[NB * NN * 2 * OD];
__device__ float g_Q[NB * NN * OD];
__device__ float g_P[NB * NN * OD];
__device__ __half g_Wt[OD * 2 * OD];  // n-major fp16: Wt[n][k]

__device__ __forceinline__ float sigmoidf_(float x) {
    return 1.0f / (1.0f + __expf(-x));
}
__device__ __forceinline__ uint32_t smem_to_u32(const void* p) {
    uint32_t a;
    asm("{ .reg .u64 t; cvta.to.shared.u64 t, %1; cvt.u32.u64 %0, t; }" : "=r"(a) : "l"(p));
    return a;
}
// pack two fp32 -> one f16x2 register (lo = x, hi = y)
__device__ __forceinline__ uint32_t pack_f16x2(float x, float y) {
    uint32_t r;
    asm("cvt.rn.f16x2.f32 %0, %2, %1;" : "=r"(r) : "f"(x), "f"(y));
    return r;
}
#define CP_ASYNC16(dst, src) \
    asm volatile("cp.async.cg.shared.global [%0], [%1], 16;" :: "r"(dst), "l"(src) : "memory")
#define CP_COMMIT() asm volatile("cp.async.commit_group;" ::: "memory")
#define CP_WAIT(n) asm volatile("cp.async.wait_group %0;" :: "n"(n) : "memory")

__device__ __forceinline__ void mma_f16(float* d, const uint32_t* a, const uint32_t* b) {
    asm volatile(
        "mma.sync.aligned.m16n8k16.row.col.f32.f16.f16.f32 "
        "{%0,%1,%2,%3}, {%4,%5,%6,%7}, {%8,%9}, {%0,%1,%2,%3};"
        : "+f"(d[0]), "+f"(d[1]), "+f"(d[2]), "+f"(d[3])
        : "r"(a[0]), "r"(a[1]), "r"(a[2]), "r"(a[3]), "r"(b[0]), "r"(b[1]));
}
__device__ __forceinline__ void ldm_x4(uint32_t& r0, uint32_t& r1, uint32_t& r2,
                                       uint32_t& r3, uint32_t addr) {
    asm volatile("ldmatrix.sync.aligned.m8n8.x4.shared.b16 {%0,%1,%2,%3}, [%4];"
                 : "=r"(r0), "=r"(r1), "=r"(r2), "=r"(r3) : "r"(addr));
}

// ---------------- fused prep: reduce2 | qp | wt | o0 (independent parts) ----
template <int D0, int D1, int D2>
__global__ void k_prep(const float* __restrict__ f0, const float* __restrict__ f1,
                       const float* __restrict__ f2, const float* __restrict__ W0,
                       const float* __restrict__ b0, const float* __restrict__ W2,
                       float* __restrict__ r2, float* __restrict__ Q,
                       float* __restrict__ P, __half* __restrict__ Wt,
                       float* __restrict__ o0) {
    constexpr int K = 2 * D2;
    int blk = blockIdx.x, t = threadIdx.x;
    if (blk < 1024) {
        // ---- reduce2: diag-masked max/min over j for (b,i)
        int i = blk & 255, b = blk >> 8;
        if (t < D2) {
            const float* base = f2 + ((size_t)(b * NN + i)) * NN * D2 + t;
            float mx = -1e30f, mn = 1e30f;
#pragma unroll 8
            for (int j = 0; j < NN; j++) {
                float v = base[(size_t)j * D2];
                mx = fmaxf(mx, (j == i) ? 0.0f : v);
                mn = fminf(mn, (j == i) ? 1.0f : v);
            }
            r2[((size_t)(b * NN + i)) * K + t] = mx;
            r2[((size_t)(b * NN + i)) * K + D2 + t] = mn;
        }
    } else if (blk < 2048) {
        // ---- qp: Q[row]=f1[row]@Wa, P[row]=f1[row]@Wc
        __shared__ float s[OD];
        int row = blk - 1024;
        if (t < D1) s[t] = f1[(size_t)row * D1 + t];
        __syncthreads();
        const float* Wa = W2;
        const float* Wc = W2 + (size_t)(D1 + D2) * OD;
        float aq = 0.0f, ap = 0.0f;
#pragma unroll 8
        for (int k = 0; k < D1; k++) {
            float v = s[k];
            aq = fmaf(v, Wa[(size_t)k * OD + t], aq);
            ap = fmaf(v, Wc[(size_t)k * OD + t], ap);
        }
        Q[(size_t)row * OD + t] = aq;
        P[(size_t)row * OD + t] = ap;
    } else if (blk < 2048 + K) {
        // ---- wt: Wt[n][k] fp16 n-major
        int k = blk - 2048;
        const float* src = (k < D2) ? W2 + (size_t)(D1 + k) * OD
                                    : W2 + (size_t)(2 * D1 + D2 + (k - D2)) * OD;
        Wt[(size_t)t * K + k] = __float2half_rn(src[t]);
    } else {
        // ---- o0
        __shared__ float sg[3 * OD];
        int b = blk - (2048 + K);
        if (t < D0) sg[t] = f0[b * D0 + t];
        if (t < D1) {
            float mx = -1e30f, mn = 1e30f;
            const float* base = f1 + (size_t)b * NN * D1 + t;
#pragma unroll 8
            for (int i2 = 0; i2 < NN; i2++) {
                float v = base[(size_t)i2 * D1];
                mx = fmaxf(mx, v);
                mn = fminf(mn, v);
            }
            sg[D0 + t] = mx;
            sg[D0 + D1 + t] = mn;
        }
        __syncthreads();
        constexpr int fan = D0 + 2 * D1;
        float acc = b0[t];
#pragma unroll 8
        for (int k = 0; k < fan; k++) acc = fmaf(sg[k], W0[(size_t)k * OD + t], acc);
        o0[b * OD + t] = sigmoidf_(acc);
    }
}

// ---------------- o1 ----------------
#define O1R 2
template <int D0, int D1, int D2>
__global__ void k_o1(const float* __restrict__ f0, const float* __restrict__ f1,
                     const float* __restrict__ r2, const float* __restrict__ W,
                     const float* __restrict__ bias, float* __restrict__ out) {
    constexpr int fan = D0 + D1 + 2 * D2;
    __shared__ float sg[O1R][fan];
    int row0 = blockIdx.x * O1R;
    int t = threadIdx.x;
    for (int idx = t; idx < O1R * fan; idx += OD) {
        int r = idx / fan, k = idx % fan;
        int row = row0 + r;
        int b = row / NN;
        float v;
        if (k < D0) v = f0[b * D0 + k];
        else if (k < D0 + D1) v = f1[(size_t)row * D1 + (k - D0)];
        else v = r2[(size_t)row * 2 * D2 + (k - D0 - D1)];
        sg[r][k] = v;
    }
    __syncthreads();
    float acc[O1R];
#pragma unroll
    for (int r = 0; r < O1R; r++) acc[r] = bias[t];
#pragma unroll 8
    for (int k = 0; k < fan; k++) {
        float w = W[(size_t)k * OD + t];
#pragma unroll
        for (int r = 0; r < O1R; r++) acc[r] = fmaf(sg[r][k], w, acc[r]);
    }
#pragma unroll
    for (int r = 0; r < O1R; r++)
        out[(size_t)(row0 + r) * OD + t] = sigmoidf_(acc[r]);
}

// ---------------- o2: mma.sync fp16 + ldmatrix, M=128 x N=128, K=2*D2 -------
#define AST 20    // A smem row stride in words (32 halves = 16 words + pad 4)
#define BST 20
#define ABUF (128 * AST)
#define BBUF (128 * BST)
#define O2_SMEM ((2 * ABUF + 2 * BBUF) * 4)

template <int D2>
__global__ void __launch_bounds__(256, 2) k_o2m(
    const float* __restrict__ f2, const float* __restrict__ Q,
    const float* __restrict__ P, const __half* __restrict__ Wt,
    const float* __restrict__ bias, float* __restrict__ out) {
    constexpr int K = 2 * D2;
    constexpr int NS = K / 32;

    extern __shared__ uint32_t smw[];
    uint32_t* Ab = smw;
    uint32_t* Bb = smw + 2 * ABUF;
    uint32_t base_u32 = smem_to_u32(smw);
    uint32_t sb_addr = base_u32 + 2 * ABUF * 4;

    int tx = threadIdx.x;
    int lane = tx & 31, warp = tx >> 5;
    int warpM = warp & 1, warpN = warp >> 1;
    int gi = lane >> 2, ci = lane & 3;
    int b = blockIdx.z, i = blockIdx.y, j0 = blockIdx.x * 128;
    size_t bi = ((size_t)(b * NN + i)) * NN;

    // ldmatrix per-lane bases (in words)
    int aRow16 = ((lane >> 3) & 1) * 8 + (lane & 7);
    int aKw = (lane >> 4) * 4;
    int bRow = ((lane >> 4) & 1) * 8 + (lane & 7);
    int bKw = ((lane >> 3) & 1) * 4;
    uint32_t aOffBase = (uint32_t)((warpM * 64 + aRow16) * AST + aKw);
    uint32_t bOffBase = (uint32_t)(2 * ABUF + (warpN * 32 + bRow) * BST + bKw);

    const float* aH1[4];
    const float* aH2[4];
#pragma unroll
    for (int it = 0; it < 4; it++) {
        int rowj = j0 + ((tx + it * 256) >> 3);
        aH1[it] = f2 + (bi + rowj) * D2;
        aH2[it] = f2 + (((size_t)(b * NN + rowj)) * NN + i) * D2 - D2;
    }

    float acc[4][4][4];
#pragma unroll
    for (int mt = 0; mt < 4; mt++)
#pragma unroll
        for (int nt = 0; nt < 4; nt++)
#pragma unroll
            for (int v = 0; v < 4; v++) acc[mt][nt][v] = 0.0f;

    // prologue: B(0) cp.async + A(0) reg prefetch
    {
#pragma unroll
        for (int it = 0; it < 2; it++) {
            int t = tx + it * 256;
            int row = t >> 2, chunk = t & 3;
            uint32_t dst = sb_addr + (uint32_t)(row * BST + chunk * 4) * 4u;
            CP_ASYNC16(dst, Wt + (size_t)row * K + chunk * 8);
        }
        CP_COMMIT();
    }
    float4 ra[4];
#pragma unroll
    for (int it = 0; it < 4; it++) {
        int q = (tx + it * 256) & 7;
        ra[it] = *(const float4*)(aH1[it] + q * 4);
    }

    for (int s = 0; s < NS; s++) {
        int p = s & 1;
#pragma unroll
        for (int it = 0; it < 4; it++) {
            int t = tx + it * 256;
            int row = t >> 3, q = t & 7;
            uint2 v;
            v.x = pack_f16x2(ra[it].x, ra[it].y);
            v.y = pack_f16x2(ra[it].z, ra[it].w);
            *(uint2*)(Ab + p * ABUF + row * AST + q * 2) = v;
        }
        __syncthreads();
        if (s + 1 < NS) {
            int c0n = (s + 1) * 32;
#pragma unroll
            for (int it = 0; it < 2; it++) {
                int t = tx + it * 256;
                int row = t >> 2, chunk = t & 3;
                uint32_t dst = sb_addr + (uint32_t)((p ^ 1) * BBUF + row * BST + chunk * 4) * 4u;
                CP_ASYNC16(dst, Wt + (size_t)row * K + c0n + chunk * 8);
            }
            CP_COMMIT();
            CP_WAIT(1);
        } else {
            CP_WAIT(0);
        }
        __syncthreads();
        if (s + 1 < NS) {
            int c0n = (s + 1) * 32;
#pragma unroll
            for (int it = 0; it < 4; it++) {
                int q = (tx + it * 256) & 7;
                const float* basep = (c0n < D2) ? aH1[it] : aH2[it];
                ra[it] = *(const float4*)(basep + c0n + q * 4);
            }
        }
        // mma: 2 k16 chunks, fragments via ldmatrix.x4
        uint32_t aStage = base_u32 + (uint32_t)(p * ABUF) * 4;
        uint32_t bStage = base_u32 + (uint32_t)(p * BBUF) * 4;
#pragma unroll
        for (int ks = 0; ks < 2; ks++) {
            uint32_t af[4][4];
#pragma unroll
            for (int mt = 0; mt < 4; mt++) {
                uint32_t addr = aStage + (aOffBase + mt * 16 * AST + ks * 8) * 4u;
                ldm_x4(af[mt][0], af[mt][1], af[mt][2], af[mt][3], addr);
            }
            uint32_t bf[4][2];
#pragma unroll
            for (int h = 0; h < 2; h++) {
                uint32_t addr = bStage + (bOffBase + h * 16 * BST + ks * 8) * 4u;
                ldm_x4(bf[2 * h][0], bf[2 * h][1], bf[2 * h + 1][0], bf[2 * h + 1][1], addr);
            }
#pragma unroll
            for (int mt = 0; mt < 4; mt++)
#pragma unroll
                for (int nt = 0; nt < 4; nt++)
                    mma_f16(acc[mt][nt], af[mt], bf[nt]);
        }
    }

    // epilogue
    __syncthreads();
    float* sQB = (float*)smw;
    if (tx < 128) sQB[tx] = Q[((size_t)(b * NN + i)) * OD + tx] + bias[tx];
    __syncthreads();
#pragma unroll
    for (int mt = 0; mt < 4; mt++) {
#pragma unroll
        for (int rr = 0; rr < 2; rr++) {
            int j = j0 + warpM * 64 + mt * 16 + gi + rr * 8;
            const float* pRow = P + ((size_t)(b * NN + j)) * OD;
            float* oRow = out + (bi + j) * OD;
#pragma unroll
            for (int nt = 0; nt < 4; nt++) {
                int col = warpN * 32 + nt * 8 + ci * 2;
                float2 p2 = *(const float2*)(pRow + col);
                float2 o;
                o.x = sigmoidf_(acc[mt][nt][rr * 2 + 0] + sQB[col + 0] + p2.x);
                o.y = sigmoidf_(acc[mt][nt][rr * 2 + 1] + sQB[col + 1] + p2.y);
                *(float2*)(oRow + col) = o;
            }
        }
    }
}

// ---------------- host side ----------------
template <int D0, int D1, int D2>
static void run_layer(const float* f0, const float* f1, const float* f2,
                      const float* W0, const float* b0,
                      const float* W1, const float* b1,
                      const float* W2, const float* b2,
                      float* o0, float* o1, float* o2,
                      float* r2, float* Q, float* P, __half* Wt) {
    cudaFuncSetAttribute(k_o2m<D2>, cudaFuncAttributeMaxDynamicSharedMemorySize, O2_SMEM);
    k_prep<D0, D1, D2><<<2048 + 2 * D2 + NB, 128>>>(f0, f1, f2, W0, b0, W2,
                                                    r2, Q, P, Wt, o0);
    k_o1<D0, D1, D2><<<NB * NN / O1R, OD>>>(f0, f1, r2, W1, b1, o1);
    k_o2m<D2><<<dim3(NN / 128, NN, NB), 256, O2_SMEM>>>(f2, Q, P, Wt, b2, o2);
}

extern "C" void kernel_launch(void* const* d_in, const int* in_sizes, int n_in,
                              void* d_out, int out_size) {
    const float* x0 = (const float*)d_in[0];
    const float* x1 = (const float*)d_in[1];
    const float* x2 = (const float*)d_in[2];
    const float* W[3][3];
    const float* Bv[3][3];
    for (int l = 0; l < 3; l++)
        for (int o = 0; o < 3; o++) {
            W[l][o] = (const float*)d_in[3 + l * 6 + o * 2];
            Bv[l][o] = (const float*)d_in[3 + l * 6 + o * 2 + 1];
        }

    float *f0a, *f0b, *f1a, *f1b, *f2a, *f2b, *r2, *Q, *P;
    __half* Wt;
    cudaGetSymbolAddress((void**)&f0a, g_f0a);
    cudaGetSymbolAddress((void**)&f0b, g_f0b);
    cudaGetSymbolAddress((void**)&f1a, g_f1a);
    cudaGetSymbolAddress((void**)&f1b, g_f1b);
    cudaGetSymbolAddress((void**)&f2a, g_f2a);
    cudaGetSymbolAddress((void**)&f2b, g_f2b);
    cudaGetSymbolAddress((void**)&r2, g_r2);
    cudaGetSymbolAddress((void**)&Q, g_Q);
    cudaGetSymbolAddress((void**)&P, g_P);
    cudaGetSymbolAddress((void**)&Wt, g_Wt);

    float* out = (float*)d_out;
    float* out0 = out;
    float* out1 = out + NB * OD;
    float* out2 = out + NB * OD + (size_t)NB * NN * OD;

    run_layer<32, 64, 64>(x0, x1, x2,
                          W[0][0], Bv[0][0], W[0][1], Bv[0][1], W[0][2], Bv[0][2],
                          f0a, f1a, f2a, r2, Q, P, Wt);
    run_layer<128, 128, 128>(f0a, f1a, f2a,
                             W[1][0], Bv[1][0], W[1][1], Bv[1][1], W[1][2], Bv[1][2],
                             f0b, f1b, f2b, r2, Q, P, Wt);
    run_layer<128, 128, 128>(f0b, f1b, f2b,
                             W[2][0], Bv[2][0], W[2][1], Bv[2][1], W[2][2], Bv[2][2],
                             out0, out1, out2, r2, Q, P, Wt);
}

// round 11
// speedup vs baseline: 2.7575x; 1.1096x over previous
#include <cuda_runtime.h>
#include <cuda_fp16.h>
#include <math.h>
#include <cstdint>

#define NB 4
#define NN 256
#define OD 128

// ---------------- scratch (device globals; no allocation) ----------------
__device__ float g_f0a[NB * OD];
__device__ float g_f0b[NB * OD];
__device__ float g_f1a[NB * NN * OD];
__device__ float g_f1b[NB * NN * OD];
__device__ __half g_h2a[(size_t)NB * NN * NN * OD];  // fp16 f2 intermediates
__device__ __half g_h2b[(size_t)NB * NN * NN * OD];
__device__ float g_r2[NB * NN * 2 * OD];
__device__ float g_Q[NB * NN * OD];
__device__ float g_P[NB * NN * OD];
__device__ __half g_Wt[OD * 2 * OD];  // n-major fp16: Wt[n][k]

__device__ __forceinline__ float sigmoidf_(float x) {
    return 1.0f / (1.0f + __expf(-x));
}
__device__ __forceinline__ uint32_t smem_to_u32(const void* p) {
    uint32_t a;
    asm("{ .reg .u64 t; cvta.to.shared.u64 t, %1; cvt.u32.u64 %0, t; }" : "=r"(a) : "l"(p));
    return a;
}
__device__ __forceinline__ uint32_t pack_f16x2(float x, float y) {
    uint32_t r;
    asm("cvt.rn.f16x2.f32 %0, %2, %1;" : "=r"(r) : "f"(x), "f"(y));
    return r;
}
#define CP_ASYNC16(dst, src) \
    asm volatile("cp.async.cg.shared.global [%0], [%1], 16;" :: "r"(dst), "l"(src) : "memory")
#define CP_COMMIT() asm volatile("cp.async.commit_group;" ::: "memory")
#define CP_WAIT(n) asm volatile("cp.async.wait_group %0;" :: "n"(n) : "memory")

__device__ __forceinline__ void mma_f16(float* d, const uint32_t* a, const uint32_t* b) {
    asm volatile(
        "mma.sync.aligned.m16n8k16.row.col.f32.f16.f16.f32 "
        "{%0,%1,%2,%3}, {%4,%5,%6,%7}, {%8,%9}, {%0,%1,%2,%3};"
        : "+f"(d[0]), "+f"(d[1]), "+f"(d[2]), "+f"(d[3])
        : "r"(a[0]), "r"(a[1]), "r"(a[2]), "r"(a[3]), "r"(b[0]), "r"(b[1]));
}
__device__ __forceinline__ void ldm_x4(uint32_t& r0, uint32_t& r1, uint32_t& r2,
                                       uint32_t& r3, uint32_t addr) {
    asm volatile("ldmatrix.sync.aligned.m8n8.x4.shared.b16 {%0,%1,%2,%3}, [%4];"
                 : "=r"(r0), "=r"(r1), "=r"(r2), "=r"(r3) : "r"(addr));
}

// ---------------- fused prep: reduce2 | qp | wt | o0 ------------------------
template <int D0, int D1, int D2, typename T2>
__global__ void k_prep(const float* __restrict__ f0, const float* __restrict__ f1,
                       const T2* __restrict__ f2, const float* __restrict__ W0,
                       const float* __restrict__ b0, const float* __restrict__ W2,
                       float* __restrict__ r2, float* __restrict__ Q,
                       float* __restrict__ P, __half* __restrict__ Wt,
                       float* __restrict__ o0) {
    constexpr int K = 2 * D2;
    int blk = blockIdx.x, t = threadIdx.x;
    __shared__ float s_qp[OD];
    __shared__ float s_o0[3 * OD];
    __shared__ __half2 sredx[8][16][4];
    __shared__ __half2 sredn[8][16][4];
    if (blk < 1024) {
        int i = blk & 255, b = blk >> 8;
        size_t rowbase = ((size_t)(b * NN + i)) * K;
        if constexpr (sizeof(T2) == 2) {
            // fp16 vectorized: 16 lanes x 8 halves cover D2=128; 8 j-groups
            int lc = t & 15, jg = t >> 4;
            const __half2 zero2 = __floats2half2_rn(0.0f, 0.0f);
            const __half2 one2 = __floats2half2_rn(1.0f, 1.0f);
            __half2 mx[4], mn[4];
#pragma unroll
            for (int q = 0; q < 4; q++) { mx[q] = zero2; mn[q] = one2; }
            const __half* base = (const __half*)f2 +
                                 ((size_t)(b * NN + i)) * NN * D2 + lc * 8;
#pragma unroll 4
            for (int j = jg; j < NN; j += 8) {
                uint4 raw = *(const uint4*)(base + (size_t)j * D2);
                __half2 v[4];
                v[0] = *(__half2*)&raw.x; v[1] = *(__half2*)&raw.y;
                v[2] = *(__half2*)&raw.z; v[3] = *(__half2*)&raw.w;
                bool diag = (j == i);
#pragma unroll
                for (int q = 0; q < 4; q++) {
                    mx[q] = __hmax2(mx[q], diag ? zero2 : v[q]);
                    mn[q] = __hmin2(mn[q], diag ? one2 : v[q]);
                }
            }
#pragma unroll
            for (int q = 0; q < 4; q++) { sredx[jg][lc][q] = mx[q]; sredn[jg][lc][q] = mn[q]; }
            __syncthreads();
            if (t < 16) {
#pragma unroll
                for (int q = 0; q < 4; q++) { mx[q] = sredx[0][t][q]; mn[q] = sredn[0][t][q]; }
#pragma unroll
                for (int g = 1; g < 8; g++)
#pragma unroll
                    for (int q = 0; q < 4; q++) {
                        mx[q] = __hmax2(mx[q], sredx[g][t][q]);
                        mn[q] = __hmin2(mn[q], sredn[g][t][q]);
                    }
#pragma unroll
                for (int q = 0; q < 4; q++) {
                    float2 fx = __half22float2(mx[q]);
                    float2 fn = __half22float2(mn[q]);
                    int d = t * 8 + q * 2;
                    r2[rowbase + d] = fx.x;
                    r2[rowbase + d + 1] = fx.y;
                    r2[rowbase + D2 + d] = fn.x;
                    r2[rowbase + D2 + d + 1] = fn.y;
                }
            }
        } else {
            if (t < D2) {
                const float* base = (const float*)f2 +
                                    ((size_t)(b * NN + i)) * NN * D2 + t;
                float mx = -1e30f, mn = 1e30f;
#pragma unroll 8
                for (int j = 0; j < NN; j++) {
                    float v = base[(size_t)j * D2];
                    mx = fmaxf(mx, (j == i) ? 0.0f : v);
                    mn = fminf(mn, (j == i) ? 1.0f : v);
                }
                r2[rowbase + t] = mx;
                r2[rowbase + D2 + t] = mn;
            }
        }
    } else if (blk < 2048) {
        int row = blk - 1024;
        if (t < D1) s_qp[t] = f1[(size_t)row * D1 + t];
        __syncthreads();
        const float* Wa = W2;
        const float* Wc = W2 + (size_t)(D1 + D2) * OD;
        float aq = 0.0f, ap = 0.0f;
#pragma unroll 8
        for (int k = 0; k < D1; k++) {
            float v = s_qp[k];
            aq = fmaf(v, Wa[(size_t)k * OD + t], aq);
            ap = fmaf(v, Wc[(size_t)k * OD + t], ap);
        }
        Q[(size_t)row * OD + t] = aq;
        P[(size_t)row * OD + t] = ap;
    } else if (blk < 2048 + K) {
        int k = blk - 2048;
        const float* src = (k < D2) ? W2 + (size_t)(D1 + k) * OD
                                    : W2 + (size_t)(2 * D1 + D2 + (k - D2)) * OD;
        Wt[(size_t)t * K + k] = __float2half_rn(src[t]);
    } else {
        int b = blk - (2048 + K);
        if (t < D0) s_o0[t] = f0[b * D0 + t];
        if (t < D1) {
            float mx = -1e30f, mn = 1e30f;
            const float* base = f1 + (size_t)b * NN * D1 + t;
#pragma unroll 8
            for (int i2 = 0; i2 < NN; i2++) {
                float v = base[(size_t)i2 * D1];
                mx = fmaxf(mx, v);
                mn = fminf(mn, v);
            }
            s_o0[D0 + t] = mx;
            s_o0[D0 + D1 + t] = mn;
        }
        __syncthreads();
        constexpr int fan = D0 + 2 * D1;
        float acc = b0[t];
#pragma unroll 8
        for (int k = 0; k < fan; k++) acc = fmaf(s_o0[k], W0[(size_t)k * OD + t], acc);
        o0[b * OD + t] = sigmoidf_(acc);
    }
}

// ---------------- o1 ----------------
#define O1R 2
template <int D0, int D1, int D2>
__global__ void k_o1(const float* __restrict__ f0, const float* __restrict__ f1,
                     const float* __restrict__ r2, const float* __restrict__ W,
                     const float* __restrict__ bias, float* __restrict__ out) {
    constexpr int fan = D0 + D1 + 2 * D2;
    __shared__ float sg[O1R][fan];
    int row0 = blockIdx.x * O1R;
    int t = threadIdx.x;
    for (int idx = t; idx < O1R * fan; idx += OD) {
        int r = idx / fan, k = idx % fan;
        int row = row0 + r;
        int b = row / NN;
        float v;
        if (k < D0) v = f0[b * D0 + k];
        else if (k < D0 + D1) v = f1[(size_t)row * D1 + (k - D0)];
        else v = r2[(size_t)row * 2 * D2 + (k - D0 - D1)];
        sg[r][k] = v;
    }
    __syncthreads();
    float acc[O1R];
#pragma unroll
    for (int r = 0; r < O1R; r++) acc[r] = bias[t];
#pragma unroll 8
    for (int k = 0; k < fan; k++) {
        float w = W[(size_t)k * OD + t];
#pragma unroll
        for (int r = 0; r < O1R; r++) acc[r] = fmaf(sg[r][k], w, acc[r]);
    }
#pragma unroll
    for (int r = 0; r < O1R; r++)
        out[(size_t)(row0 + r) * OD + t] = sigmoidf_(acc[r]);
}

// ---------------- o2: mma.sync fp16 + ldmatrix ------------------------------
#define AST 20
#define BST 20
#define ABUF (128 * AST)
#define BBUF (128 * BST)
#define O2_SMEM ((2 * ABUF + 2 * BBUF) * 4)

template <int D2, bool INH, bool OUTH>
__global__ void __launch_bounds__(256, 2) k_o2m(
    const void* __restrict__ f2v, const float* __restrict__ Q,
    const float* __restrict__ P, const __half* __restrict__ Wt,
    const float* __restrict__ bias, void* __restrict__ outv) {
    constexpr int K = 2 * D2;
    constexpr int NS = K / 32;

    extern __shared__ uint32_t smw[];
    uint32_t* Ab = smw;
    uint32_t base_u32 = smem_to_u32(smw);
    uint32_t sb_addr = base_u32 + 2 * ABUF * 4;

    int tx = threadIdx.x;
    int lane = tx & 31, warp = tx >> 5;
    int warpM = warp & 1, warpN = warp >> 1;
    int gi = lane >> 2, ci = lane & 3;
    int b = blockIdx.z, i = blockIdx.y, j0 = blockIdx.x * 128;
    size_t bi = ((size_t)(b * NN + i)) * NN;

    int aRow16 = ((lane >> 3) & 1) * 8 + (lane & 7);
    int aKw = (lane >> 4) * 4;
    int bRow = ((lane >> 4) & 1) * 8 + (lane & 7);
    int bKw = ((lane >> 3) & 1) * 4;
    uint32_t aOffBase = (uint32_t)((warpM * 64 + aRow16) * AST + aKw);
    uint32_t bOffBase = (uint32_t)(2 * ABUF + (warpN * 32 + bRow) * BST + bKw);

    float acc[4][4][4];
#pragma unroll
    for (int mt = 0; mt < 4; mt++)
#pragma unroll
        for (int nt = 0; nt < 4; nt++)
#pragma unroll
            for (int v = 0; v < 4; v++) acc[mt][nt][v] = 0.0f;

    // shared mma step
    auto doMMA = [&](int p) {
        uint32_t aStage = base_u32 + (uint32_t)(p * ABUF) * 4;
        uint32_t bStage = base_u32 + (uint32_t)((2 * ABUF) + p * BBUF) * 4;
#pragma unroll
        for (int ks = 0; ks < 2; ks++) {
            uint32_t af[4][4];
#pragma unroll
            for (int mt = 0; mt < 4; mt++) {
                uint32_t addr = aStage + (uint32_t)((warpM * 64 + aRow16) * AST + aKw + mt * 16 * AST + ks * 8) * 4u;
                ldm_x4(af[mt][0], af[mt][1], af[mt][2], af[mt][3], addr);
            }
            uint32_t bf[4][2];
#pragma unroll
            for (int h = 0; h < 2; h++) {
                uint32_t addr = bStage + (uint32_t)((warpN * 32 + bRow) * BST + bKw + h * 16 * BST + ks * 8) * 4u;
                ldm_x4(bf[2 * h][0], bf[2 * h][1], bf[2 * h + 1][0], bf[2 * h + 1][1], addr);
            }
#pragma unroll
            for (int mt = 0; mt < 4; mt++)
#pragma unroll
                for (int nt = 0; nt < 4; nt++)
                    mma_f16(acc[mt][nt], af[mt], bf[nt]);
        }
    };
    (void)aOffBase; (void)bOffBase;

    auto fillB = [&](int p, int c0) {
#pragma unroll
        for (int it = 0; it < 2; it++) {
            int t = tx + it * 256;
            int row = t >> 2, chunk = t & 3;
            uint32_t dst = sb_addr + (uint32_t)(p * BBUF + row * BST + chunk * 4) * 4u;
            CP_ASYNC16(dst, Wt + (size_t)row * K + c0 + chunk * 8);
        }
    };

    if constexpr (INH) {
        const __half* f2h = (const __half*)f2v;
        const __half* hH1[2];
        const __half* hH2[2];
#pragma unroll
        for (int it = 0; it < 2; it++) {
            int rowj = j0 + (tx >> 2) + it * 64;
            hH1[it] = f2h + (bi + rowj) * D2;
            hH2[it] = f2h + (((size_t)(b * NN + rowj)) * NN + i) * D2 - D2;
        }
        int cc = (tx & 3) * 8;
        auto fillA = [&](int p, int c0) {
#pragma unroll
            for (int it = 0; it < 2; it++) {
                int row = (tx >> 2) + it * 64;
                const __half* src = ((c0 < D2) ? hH1[it] : hH2[it]) + c0 + cc;
                uint32_t dst = base_u32 + (uint32_t)(p * ABUF + row * AST + (tx & 3) * 4) * 4u;
                CP_ASYNC16(dst, src);
            }
        };
        fillA(0, 0);
        fillB(0, 0);
        CP_COMMIT();
        for (int s = 0; s < NS; s++) {
            int p = s & 1;
            if (s + 1 < NS) {
                fillA(p ^ 1, (s + 1) * 32);
                fillB(p ^ 1, (s + 1) * 32);
                CP_COMMIT();
                CP_WAIT(1);
            } else {
                CP_WAIT(0);
            }
            __syncthreads();
            doMMA(p);
            __syncthreads();
        }
    } else {
        const float* f2 = (const float*)f2v;
        const float* aH1[4];
        const float* aH2[4];
#pragma unroll
        for (int it = 0; it < 4; it++) {
            int rowj = j0 + ((tx + it * 256) >> 3);
            aH1[it] = f2 + (bi + rowj) * D2;
            aH2[it] = f2 + (((size_t)(b * NN + rowj)) * NN + i) * D2 - D2;
        }
        fillB(0, 0);
        CP_COMMIT();
        float4 ra[4];
#pragma unroll
        for (int it = 0; it < 4; it++) {
            int q = (tx + it * 256) & 7;
            ra[it] = *(const float4*)(aH1[it] + q * 4);
        }
        for (int s = 0; s < NS; s++) {
            int p = s & 1;
#pragma unroll
            for (int it = 0; it < 4; it++) {
                int t = tx + it * 256;
                int row = t >> 3, q = t & 7;
                uint2 v;
                v.x = pack_f16x2(ra[it].x, ra[it].y);
                v.y = pack_f16x2(ra[it].z, ra[it].w);
                *(uint2*)(Ab + p * ABUF + row * AST + q * 2) = v;
            }
            __syncthreads();
            if (s + 1 < NS) {
                fillB(p ^ 1, (s + 1) * 32);
                CP_COMMIT();
                CP_WAIT(1);
            } else {
                CP_WAIT(0);
            }
            __syncthreads();
            if (s + 1 < NS) {
                int c0n = (s + 1) * 32;
#pragma unroll
                for (int it = 0; it < 4; it++) {
                    int q = (tx + it * 256) & 7;
                    const float* basep = (c0n < D2) ? aH1[it] : aH2[it];
                    ra[it] = *(const float4*)(basep + c0n + q * 4);
                }
            }
            doMMA(p);
        }
    }

    // epilogue
    __syncthreads();
    float* sQB = (float*)smw;
    if (tx < 128) sQB[tx] = Q[((size_t)(b * NN + i)) * OD + tx] + bias[tx];
    __syncthreads();
#pragma unroll
    for (int mt = 0; mt < 4; mt++) {
#pragma unroll
        for (int rr = 0; rr < 2; rr++) {
            int j = j0 + warpM * 64 + mt * 16 + gi + rr * 8;
            const float* pRow = P + ((size_t)(b * NN + j)) * OD;
#pragma unroll
            for (int nt = 0; nt < 4; nt++) {
                int col = warpN * 32 + nt * 8 + ci * 2;
                float2 p2 = *(const float2*)(pRow + col);
                float ox = sigmoidf_(acc[mt][nt][rr * 2 + 0] + sQB[col + 0] + p2.x);
                float oy = sigmoidf_(acc[mt][nt][rr * 2 + 1] + sQB[col + 1] + p2.y);
                if constexpr (OUTH) {
                    __half* oRow = (__half*)outv + (bi + j) * OD;
                    *(uint32_t*)(oRow + col) = pack_f16x2(ox, oy);
                } else {
                    float* oRow = (float*)outv + (bi + j) * OD;
                    float2 o;
                    o.x = ox; o.y = oy;
                    *(float2*)(oRow + col) = o;
                }
            }
        }
    }
}

// ---------------- host side ----------------
template <int D0, int D1, int D2, typename T2, bool OUTH>
static void run_layer(const float* f0, const float* f1, const T2* f2,
                      const float* W0, const float* b0,
                      const float* W1, const float* b1,
                      const float* W2, const float* b2,
                      float* o0, float* o1, void* o2,
                      float* r2, float* Q, float* P, __half* Wt) {
    constexpr bool INH = (sizeof(T2) == 2);
    cudaFuncSetAttribute(k_o2m<D2, INH, OUTH>,
                         cudaFuncAttributeMaxDynamicSharedMemorySize, O2_SMEM);
    k_prep<D0, D1, D2, T2><<<2048 + 2 * D2 + NB, 128>>>(f0, f1, f2, W0, b0, W2,
                                                        r2, Q, P, Wt, o0);
    k_o1<D0, D1, D2><<<NB * NN / O1R, OD>>>(f0, f1, r2, W1, b1, o1);
    k_o2m<D2, INH, OUTH><<<dim3(NN / 128, NN, NB), 256, O2_SMEM>>>(
        f2, Q, P, Wt, b2, o2);
}

extern "C" void kernel_launch(void* const* d_in, const int* in_sizes, int n_in,
                              void* d_out, int out_size) {
    const float* x0 = (const float*)d_in[0];
    const float* x1 = (const float*)d_in[1];
    const float* x2 = (const float*)d_in[2];
    const float* W[3][3];
    const float* Bv[3][3];
    for (int l = 0; l < 3; l++)
        for (int o = 0; o < 3; o++) {
            W[l][o] = (const float*)d_in[3 + l * 6 + o * 2];
            Bv[l][o] = (const float*)d_in[3 + l * 6 + o * 2 + 1];
        }

    float *f0a, *f0b, *f1a, *f1b, *r2, *Q, *P;
    __half *h2a, *h2b, *Wt;
    cudaGetSymbolAddress((void**)&f0a, g_f0a);
    cudaGetSymbolAddress((void**)&f0b, g_f0b);
    cudaGetSymbolAddress((void**)&f1a, g_f1a);
    cudaGetSymbolAddress((void**)&f1b, g_f1b);
    cudaGetSymbolAddress((void**)&h2a, g_h2a);
    cudaGetSymbolAddress((void**)&h2b, g_h2b);
    cudaGetSymbolAddress((void**)&r2, g_r2);
    cudaGetSymbolAddress((void**)&Q, g_Q);
    cudaGetSymbolAddress((void**)&P, g_P);
    cudaGetSymbolAddress((void**)&Wt, g_Wt);

    float* out = (float*)d_out;
    float* out0 = out;
    float* out1 = out + NB * OD;
    float* out2 = out + NB * OD + (size_t)NB * NN * OD;

    // layer 0: fp32 in, fp16 out
    run_layer<32, 64, 64, float, true>(x0, x1, x2,
                                       W[0][0], Bv[0][0], W[0][1], Bv[0][1],
                                       W[0][2], Bv[0][2],
                                       f0a, f1a, h2a, r2, Q, P, Wt);
    // layer 1: fp16 in, fp16 out
    run_layer<128, 128, 128, __half, true>(f0a, f1a, h2a,
                                           W[1][0], Bv[1][0], W[1][1], Bv[1][1],
                                           W[1][2], Bv[1][2],
                                           f0b, f1b, h2b, r2, Q, P, Wt);
    // layer 2: fp16 in, fp32 out (to d_out)
    run_layer<128, 128, 128, __half, false>(f0b, f1b, h2b,
                                            W[2][0], Bv[2][0], W[2][1], Bv[2][1],
                                            W[2][2], Bv[2][2],
                                            out0, out1, out2, r2, Q, P, Wt);
}